// round 9
// baseline (speedup 1.0000x reference)
#include <cuda_runtime.h>
#include <cuda_bf16.h>
#include <math.h>
#include <stdint.h>

#define B_SZ   1024
#define NLAYER 4
#define MROWS  65536
#define VELEMS ((size_t)B_SZ * NLAYER * 64 * 256)

// ---------------- scratch (static device globals; no allocation) ----------------
__device__ __align__(16) __nv_bfloat16 g_Hhi[(size_t)MROWS * 256];
__device__ __align__(16) __nv_bfloat16 g_Hlo[(size_t)MROWS * 256];
__device__ __align__(16) float         g_Q[(size_t)MROWS * 256];
__device__ __align__(16) float         g_K[(size_t)MROWS * 256];
__device__ __align__(16) float         g_Wt[2 * 256 * 256];
__device__ __align__(16) __nv_bfloat16 g_THhi[4 * 256 * 768];
__device__ __align__(16) __nv_bfloat16 g_THlo[4 * 256 * 768];

// ---------------- helpers ----------------
__device__ __forceinline__ uint32_t smem_u32(const void* p) {
    uint32_t a;
    asm("{ .reg .u64 t; cvta.to.shared.u64 t, %1; cvt.u32.u64 %0, t; }" : "=r"(a) : "l"(p));
    return a;
}
__device__ __forceinline__ void ldsm_x4(uint32_t* r, uint32_t a) {
    asm volatile("ldmatrix.sync.aligned.m8n8.x4.shared.b16 {%0,%1,%2,%3}, [%4];"
                 : "=r"(r[0]), "=r"(r[1]), "=r"(r[2]), "=r"(r[3]) : "r"(a));
}
__device__ __forceinline__ void ldsm_x4t(uint32_t* r, uint32_t a) {
    asm volatile("ldmatrix.sync.aligned.m8n8.x4.trans.shared.b16 {%0,%1,%2,%3}, [%4];"
                 : "=r"(r[0]), "=r"(r[1]), "=r"(r[2]), "=r"(r[3]) : "r"(a));
}
__device__ __forceinline__ void mma_bf16(float* d, const uint32_t* a, uint32_t b0, uint32_t b1) {
    asm volatile("mma.sync.aligned.m16n8k16.row.col.f32.bf16.bf16.f32 "
                 "{%0,%1,%2,%3}, {%4,%5,%6,%7}, {%8,%9}, {%0,%1,%2,%3};"
                 : "+f"(d[0]), "+f"(d[1]), "+f"(d[2]), "+f"(d[3])
                 : "r"(a[0]), "r"(a[1]), "r"(a[2]), "r"(a[3]), "r"(b0), "r"(b1));
}
__device__ __forceinline__ void mma_tf32(float* d, const uint32_t* a, uint32_t b0, uint32_t b1) {
    asm volatile("mma.sync.aligned.m16n8k8.row.col.f32.tf32.tf32.f32 "
                 "{%0,%1,%2,%3}, {%4,%5,%6,%7}, {%8,%9}, {%0,%1,%2,%3};"
                 : "+f"(d[0]), "+f"(d[1]), "+f"(d[2]), "+f"(d[3])
                 : "r"(a[0]), "r"(a[1]), "r"(a[2]), "r"(a[3]), "r"(b0), "r"(b1));
}
__device__ __forceinline__ uint32_t f2tf32(float f) {
    uint32_t r; asm("cvt.rna.tf32.f32 %0, %1;" : "=r"(r) : "f"(f)); return r;
}
__device__ __forceinline__ void bsplit(float v, __nv_bfloat16& h, __nv_bfloat16& l) {
    h = __float2bfloat16(v);
    l = __float2bfloat16(v - __bfloat162float(h));
}

// ---------------- prep kernels ----------------
__global__ __launch_bounds__(256) void split_x_k(
    const float* __restrict__ x, __nv_bfloat16* __restrict__ hhi,
    __nv_bfloat16* __restrict__ hlo)
{
    int e = blockIdx.x * 256 + threadIdx.x;   // one float4 per thread
    float4 v = reinterpret_cast<const float4*>(x)[e];
    __nv_bfloat16 h0, l0, h1, l1, h2, l2, h3, l3;
    bsplit(v.x, h0, l0); bsplit(v.y, h1, l1);
    bsplit(v.z, h2, l2); bsplit(v.w, h3, l3);
    size_t o = (size_t)e * 4;
    __nv_bfloat162 a; a.x = h0; a.y = h1;
    __nv_bfloat162 b; b.x = h2; b.y = h3;
    __nv_bfloat162 c; c.x = l0; c.y = l1;
    __nv_bfloat162 d; d.x = l2; d.y = l3;
    reinterpret_cast<__nv_bfloat162*>(hhi + o)[0] = a;
    reinterpret_cast<__nv_bfloat162*>(hhi + o)[1] = b;
    reinterpret_cast<__nv_bfloat162*>(hlo + o)[0] = c;
    reinterpret_cast<__nv_bfloat162*>(hlo + o)[1] = d;
}

__global__ __launch_bounds__(256) void prep_wt_k(
    const float* __restrict__ Wq, const float* __restrict__ Wk, float* __restrict__ Wt)
{
    int i = blockIdx.x * 256 + threadIdx.x;   // 131072
    int mat = i >> 16, rem = i & 65535;
    int n = rem >> 8, k = rem & 255;
    Wt[i] = (mat ? Wk : Wq)[k * 256 + n];
}

__global__ __launch_bounds__(256) void prep_th_k(
    const float* __restrict__ theta,
    __nv_bfloat16* __restrict__ thi, __nv_bfloat16* __restrict__ tlo)
{
    int idx = blockIdx.x * 256 + threadIdx.x;   // 786432 total
    int l = idx / 196608, rem = idx % 196608;
    int n = rem / 768, k = rem % 768;
    float v = theta[(size_t)l * 196608 + (size_t)k * 256 + n];
    __nv_bfloat16 h, lo; bsplit(v, h, lo);
    thi[(size_t)l * 196608 + (size_t)n * 768 + k] = h;
    tlo[(size_t)l * 196608 + (size_t)n * 768 + k] = lo;
}

// ---------------- QK projection: 3xTF32 mma (proven R8) ----------------
#define QK_SMEM (18432 * 4)

__global__ __launch_bounds__(256, 2) void qk_tf32(
    const float* __restrict__ X, const float* __restrict__ Wt,
    const float* __restrict__ bias, float* __restrict__ C)
{
    extern __shared__ float sm[];
    float* xs_h = sm;
    float* xs_l = sm + 4608;
    float* ws_h = sm + 9216;
    float* ws_l = sm + 13824;

    const int t = threadIdx.x, lane = t & 31, w = t >> 5;
    const int wm = w >> 2, wn = w & 3;
    const int m0 = blockIdx.y * 128, n0 = blockIdx.x * 128;

    float acc[4][4][4];
#pragma unroll
    for (int i = 0; i < 4; ++i)
#pragma unroll
        for (int j = 0; j < 4; ++j)
#pragma unroll
            for (int q = 0; q < 4; ++q) acc[i][j][q] = 0.f;

    float4 px[4], pw[4];
#pragma unroll
    for (int i = 0; i < 4; ++i) {
        int e = t + i * 256, r = e >> 3, q = e & 7;
        px[i] = *reinterpret_cast<const float4*>(X  + (size_t)(m0 + r) * 256 + q * 4);
        pw[i] = *reinterpret_cast<const float4*>(Wt + (size_t)(n0 + r) * 256 + q * 4);
    }

    for (int c = 0; c < 8; ++c) {
        __syncthreads();
#pragma unroll
        for (int i = 0; i < 4; ++i) {
            int e = t + i * 256, r = e >> 3, q = e & 7;
            int base = r * 36 + q * 4;
            float vx[4] = {px[i].x, px[i].y, px[i].z, px[i].w};
            float vw[4] = {pw[i].x, pw[i].y, pw[i].z, pw[i].w};
#pragma unroll
            for (int j = 0; j < 4; ++j) {
                float xh = __uint_as_float(f2tf32(vx[j]));
                xs_h[base + j] = xh;
                xs_l[base + j] = __uint_as_float(f2tf32(vx[j] - xh));
                float wh = __uint_as_float(f2tf32(vw[j]));
                ws_h[base + j] = wh;
                ws_l[base + j] = __uint_as_float(f2tf32(vw[j] - wh));
            }
        }
        if (c < 7) {
#pragma unroll
            for (int i = 0; i < 4; ++i) {
                int e = t + i * 256, r = e >> 3, q = e & 7;
                px[i] = *reinterpret_cast<const float4*>(
                    X  + (size_t)(m0 + r) * 256 + (c + 1) * 32 + q * 4);
                pw[i] = *reinterpret_cast<const float4*>(
                    Wt + (size_t)(n0 + r) * 256 + (c + 1) * 32 + q * 4);
            }
        }
        __syncthreads();

#pragma unroll
        for (int ks = 0; ks < 4; ++ks) {
            const int cc = ks * 8 + (lane & 3);
            uint32_t bh[4][2], bl[4][2];
#pragma unroll
            for (int nt = 0; nt < 4; ++nt) {
                int n = wn * 32 + nt * 8 + (lane >> 2);
                bh[nt][0] = __float_as_uint(ws_h[n * 36 + cc]);
                bh[nt][1] = __float_as_uint(ws_h[n * 36 + cc + 4]);
                bl[nt][0] = __float_as_uint(ws_l[n * 36 + cc]);
                bl[nt][1] = __float_as_uint(ws_l[n * 36 + cc + 4]);
            }
#pragma unroll
            for (int mt = 0; mt < 4; ++mt) {
                int r0 = wm * 64 + mt * 16 + (lane >> 2);
                uint32_t ah[4], al[4];
                ah[0] = __float_as_uint(xs_h[r0 * 36 + cc]);
                ah[1] = __float_as_uint(xs_h[(r0 + 8) * 36 + cc]);
                ah[2] = __float_as_uint(xs_h[r0 * 36 + cc + 4]);
                ah[3] = __float_as_uint(xs_h[(r0 + 8) * 36 + cc + 4]);
                al[0] = __float_as_uint(xs_l[r0 * 36 + cc]);
                al[1] = __float_as_uint(xs_l[(r0 + 8) * 36 + cc]);
                al[2] = __float_as_uint(xs_l[r0 * 36 + cc + 4]);
                al[3] = __float_as_uint(xs_l[(r0 + 8) * 36 + cc + 4]);
#pragma unroll
                for (int nt = 0; nt < 4; ++nt) {
                    mma_tf32(acc[mt][nt], ah, bh[nt][0], bh[nt][1]);
                    mma_tf32(acc[mt][nt], ah, bl[nt][0], bl[nt][1]);
                    mma_tf32(acc[mt][nt], al, bh[nt][0], bh[nt][1]);
                }
            }
        }
    }

#pragma unroll
    for (int mt = 0; mt < 4; ++mt)
#pragma unroll
        for (int nt = 0; nt < 4; ++nt) {
            int n = n0 + wn * 32 + nt * 8 + (lane & 3) * 2;
            float b0 = bias[n], b1 = bias[n + 1];
#pragma unroll
            for (int hf = 0; hf < 2; ++hf) {
                int m = m0 + wm * 64 + mt * 16 + (lane >> 2) + hf * 8;
                float2 vv = make_float2(acc[mt][nt][hf * 2] + b0,
                                        acc[mt][nt][hf * 2 + 1] + b1);
                *reinterpret_cast<float2*>(C + (size_t)m * 256 + n) = vv;
            }
        }
}

// ---------------- attention -> normalized adjacency (proven) ----------------
__global__ __launch_bounds__(256) void attn_k(
    const float* __restrict__ Q, const float* __restrict__ Kmat,
    float* __restrict__ Aout)
{
    extern __shared__ float sm[];
    float* qs  = sm;
    float* ks  = sm + 4096;
    float* adj = sm + 8192;
    __shared__ float deg[64];

    const int b = blockIdx.x, t = threadIdx.x;
    const int i = t >> 2, g = t & 3;

    for (int e = t; e < 4096; e += 256) adj[e] = 0.f;

    for (int h = 0; h < 4; ++h) {
        __syncthreads();
        for (int e = t; e < 4096; e += 256) {
            int n = e >> 6, d = e & 63;
            size_t base = ((size_t)b * 64 + n) * 256 + h * 64 + d;
            qs[e] = Q[base];
            ks[e] = Kmat[base];
        }
        __syncthreads();

        float s[16];
#pragma unroll
        for (int jj = 0; jj < 16; ++jj) s[jj] = 0.f;
        for (int d = 0; d < 64; ++d) {
            float qv = qs[i * 64 + d];
#pragma unroll
            for (int jj = 0; jj < 16; ++jj)
                s[jj] += qv * ks[(g * 16 + jj) * 64 + d];
        }
        float mx = -INFINITY;
#pragma unroll
        for (int jj = 0; jj < 16; ++jj) { s[jj] *= 1.25e8f; mx = fmaxf(mx, s[jj]); }
        mx = fmaxf(mx, __shfl_xor_sync(0xffffffffu, mx, 1));
        mx = fmaxf(mx, __shfl_xor_sync(0xffffffffu, mx, 2));
        float sum = 0.f;
#pragma unroll
        for (int jj = 0; jj < 16; ++jj) { s[jj] = __expf(s[jj] - mx); sum += s[jj]; }
        sum += __shfl_xor_sync(0xffffffffu, sum, 1);
        sum += __shfl_xor_sync(0xffffffffu, sum, 2);
        float inv = 0.25f / sum;
#pragma unroll
        for (int jj = 0; jj < 16; ++jj)
            adj[i * 64 + g * 16 + jj] += s[jj] * inv;
    }
    __syncthreads();

    float sv[16];
#pragma unroll
    for (int jj = 0; jj < 16; ++jj) {
        int j = g * 16 + jj;
        sv[jj] = 0.5f * (adj[i * 64 + j] + adj[j * 64 + i]);
    }
    __syncthreads();
#pragma unroll
    for (int jj = 0; jj < 16; ++jj) adj[i * 64 + g * 16 + jj] = sv[jj];

    float ds = 0.f;
#pragma unroll
    for (int jj = 0; jj < 16; ++jj) ds += sv[jj];
    ds += __shfl_xor_sync(0xffffffffu, ds, 1);
    ds += __shfl_xor_sync(0xffffffffu, ds, 2);
    if (g == 0) deg[i] = rsqrtf(ds);
    __syncthreads();

    float di = deg[i];
#pragma unroll
    for (int jj = 0; jj < 16; ++jj) {
        int j = g * 64 / 64 * 16 + jj;   // == g*16 + jj
        Aout[(size_t)b * 4096 + i * 64 + (g * 16 + jj)] = di * adj[i * 64 + g * 16 + jj] * deg[g * 16 + jj];
    }
}

// ---------------- fused Chebyshev + theta layer (one block per batch) ----------------
// smem bf16 elem offsets: Lt hi/lo (64x72), hbuf hi/lo (64x264), z1 hi/lo (64x264),
// theta B-stage hi/lo (256x40).
#define F_LTH 0
#define F_LTL 4608
#define F_HBH 9216
#define F_HBL 26112
#define F_Z1H 43008
#define F_Z1L 59904
#define F_BH  76800
#define F_BL  87040
#define FUSED_SMEM (97280 * 2)

// z-step: out[8][4] = Lt @ src  (bf16x3). Warp tile 16 rows x 64 cols.
__device__ __forceinline__ void zstep(
    uint32_t sb, int wm, int wn, int lane, int srcH, float out[8][4])
{
#pragma unroll
    for (int j = 0; j < 8; ++j)
#pragma unroll
        for (int q = 0; q < 4; ++q) out[j][q] = 0.f;

#pragma unroll
    for (int ks = 0; ks < 4; ++ks) {
        uint32_t ao = sb + 2 * (F_LTH + (wm * 16 + (lane & 15)) * 72
                                + ks * 16 + (lane >> 4) * 8);
        uint32_t ah[4], al[4];
        ldsm_x4(ah, ao);
        ldsm_x4(al, ao + 2 * 4608);
#pragma unroll
        for (int np = 0; np < 4; ++np) {
            uint32_t bo = sb + 2 * (srcH + (ks * 16 + (lane & 15)) * 264
                                    + wn * 64 + np * 16 + (lane >> 4) * 8);
            uint32_t bh[4], bl[4];
            ldsm_x4t(bh, bo);
            ldsm_x4t(bl, bo + 2 * 16896);
#pragma unroll
            for (int s = 0; s < 2; ++s) {
                int j = np * 2 + s;
                mma_bf16(out[j], ah, bh[2 * s], bh[2 * s + 1]);
                mma_bf16(out[j], ah, bl[2 * s], bl[2 * s + 1]);
                mma_bf16(out[j], al, bh[2 * s], bh[2 * s + 1]);
            }
        }
    }
}

// theta section: acc += src @ TH[koff..koff+256)^T (bf16x3), B streamed via smem stage.
__device__ __forceinline__ void theta_section(
    uint32_t sb, __nv_bfloat16* S, int t, int lane, int wm, int wn,
    int srcH, int koff,
    const __nv_bfloat16* __restrict__ THh, const __nv_bfloat16* __restrict__ THl,
    float acc[8][4])
{
    const int bn = t >> 1, bk = (t & 1) * 16;
    const size_t gsrc = (size_t)bn * 768 + koff + bk;

    uint4 p0 = *reinterpret_cast<const uint4*>(THh + gsrc);
    uint4 p1 = *reinterpret_cast<const uint4*>(THh + gsrc + 8);
    uint4 p2 = *reinterpret_cast<const uint4*>(THl + gsrc);
    uint4 p3 = *reinterpret_cast<const uint4*>(THl + gsrc + 8);

    for (int c = 0; c < 8; ++c) {
        __syncthreads();   // stage free (prev chunk mma done)
        *reinterpret_cast<uint4*>(&S[F_BH + bn * 40 + bk])     = p0;
        *reinterpret_cast<uint4*>(&S[F_BH + bn * 40 + bk + 8]) = p1;
        *reinterpret_cast<uint4*>(&S[F_BL + bn * 40 + bk])     = p2;
        *reinterpret_cast<uint4*>(&S[F_BL + bn * 40 + bk + 8]) = p3;
        if (c < 7) {
            size_t g2 = gsrc + (c + 1) * 32;
            p0 = *reinterpret_cast<const uint4*>(THh + g2);
            p1 = *reinterpret_cast<const uint4*>(THh + g2 + 8);
            p2 = *reinterpret_cast<const uint4*>(THl + g2);
            p3 = *reinterpret_cast<const uint4*>(THl + g2 + 8);
        }
        __syncthreads();   // stage ready

#pragma unroll
        for (int ks = 0; ks < 2; ++ks) {
            uint32_t ao = sb + 2 * (srcH + (wm * 16 + (lane & 15)) * 264
                                    + c * 32 + ks * 16 + (lane >> 4) * 8);
            uint32_t ah[4], al[4];
            ldsm_x4(ah, ao);
            ldsm_x4(al, ao + 2 * 16896);
#pragma unroll
            for (int nt = 0; nt < 4; ++nt) {
                uint32_t bo = sb + 2 * (F_BH + (wn * 64 + nt * 16 + (lane & 15)) * 40
                                        + ks * 16 + (lane >> 4) * 8);
                uint32_t bh[4], bl[4];
                ldsm_x4(bh, bo);
                ldsm_x4(bl, bo + 2 * 10240);
#pragma unroll
                for (int s = 0; s < 2; ++s) {
                    int j = nt * 2 + s;
                    mma_bf16(acc[j], ah, bh[s], bh[s + 2]);
                    mma_bf16(acc[j], ah, bl[s], bl[s + 2]);
                    mma_bf16(acc[j], al, bh[s], bh[s + 2]);
                }
            }
        }
    }
}

__global__ __launch_bounds__(512, 1) void fused_layer(
    const float* __restrict__ Aglob,
    const __nv_bfloat16* __restrict__ THh, const __nv_bfloat16* __restrict__ THl,
    __nv_bfloat16* __restrict__ Hhi, __nv_bfloat16* __restrict__ Hlo,
    float* __restrict__ Vout, int writeH, int layer)
{
    extern __shared__ __nv_bfloat16 S[];
    const uint32_t sb = smem_u32(S);
    const int b = blockIdx.x;
    const int t = threadIdx.x, lane = t & 31, w = t >> 5;
    const int wm = w >> 2, wn = w & 3;

    // Lt = -A[b] split hi/lo
    {
        const float4* Ab = reinterpret_cast<const float4*>(Aglob + (size_t)b * 4096);
#pragma unroll
        for (int i = 0; i < 2; ++i) {
            int e = i * 512 + t;
            int r = e >> 4, q = (e & 15) * 4;
            float4 v = Ab[e];
            float vv[4] = {-v.x, -v.y, -v.z, -v.w};
            __nv_bfloat16 hh[4], ll[4];
#pragma unroll
            for (int j = 0; j < 4; ++j) bsplit(vv[j], hh[j], ll[j]);
            __nv_bfloat162 p0; p0.x = hh[0]; p0.y = hh[1];
            __nv_bfloat162 p1; p1.x = hh[2]; p1.y = hh[3];
            __nv_bfloat162 q0; q0.x = ll[0]; q0.y = ll[1];
            __nv_bfloat162 q1; q1.x = ll[2]; q1.y = ll[3];
            *reinterpret_cast<__nv_bfloat162*>(&S[F_LTH + r * 72 + q])     = p0;
            *reinterpret_cast<__nv_bfloat162*>(&S[F_LTH + r * 72 + q + 2]) = p1;
            *reinterpret_cast<__nv_bfloat162*>(&S[F_LTL + r * 72 + q])     = q0;
            *reinterpret_cast<__nv_bfloat162*>(&S[F_LTL + r * 72 + q + 2]) = q1;
        }
    }
    // h hi/lo from global H
    {
#pragma unroll
        for (int i = 0; i < 4; ++i) {
            int e = i * 512 + t;
            int r = e >> 5, q = (e & 31) * 8;
            size_t src = (size_t)(b * 64 + r) * 256 + q;
            *reinterpret_cast<uint4*>(&S[F_HBH + r * 264 + q]) =
                *reinterpret_cast<const uint4*>(Hhi + src);
            *reinterpret_cast<uint4*>(&S[F_HBL + r * 264 + q]) =
                *reinterpret_cast<const uint4*>(Hlo + src);
        }
    }
    __syncthreads();

    // ---- z1 = Lt @ h -> z1buf ----
    {
        float zf[8][4];
        zstep(sb, wm, wn, lane, F_HBH, zf);
#pragma unroll
        for (int j = 0; j < 8; ++j) {
            int col = wn * 64 + j * 8 + (lane & 3) * 2;
#pragma unroll
            for (int hf = 0; hf < 2; ++hf) {
                int row = wm * 16 + (lane >> 2) + hf * 8;
                __nv_bfloat16 h0, l0, h1, l1;
                bsplit(zf[j][hf * 2], h0, l0);
                bsplit(zf[j][hf * 2 + 1], h1, l1);
                __nv_bfloat162 ph; ph.x = h0; ph.y = h1;
                __nv_bfloat162 pl; pl.x = l0; pl.y = l1;
                *reinterpret_cast<__nv_bfloat162*>(&S[F_Z1H + row * 264 + col]) = ph;
                *reinterpret_cast<__nv_bfloat162*>(&S[F_Z1L + row * 264 + col]) = pl;
            }
        }
    }
    __syncthreads();

    float acc[8][4];
#pragma unroll
    for (int j = 0; j < 8; ++j)
#pragma unroll
        for (int q = 0; q < 4; ++q) acc[j][q] = 0.f;

    // ---- theta section 0: acc += h @ th0 ----
    theta_section(sb, S, t, lane, wm, wn, F_HBH, 0, THh, THl, acc);

    // ---- z2 = 2 * (Lt @ z1) - h  (regs), then overwrite hbuf ----
    {
        float zf[8][4];
        zstep(sb, wm, wn, lane, F_Z1H, zf);
        // subtract h (read before overwrite)
        float z2v[8][4];
#pragma unroll
        for (int j = 0; j < 8; ++j) {
            int col = wn * 64 + j * 8 + (lane & 3) * 2;
#pragma unroll
            for (int hf = 0; hf < 2; ++hf) {
                int row = wm * 16 + (lane >> 2) + hf * 8;
                __nv_bfloat162 hh = *reinterpret_cast<const __nv_bfloat162*>(&S[F_HBH + row * 264 + col]);
                __nv_bfloat162 hl = *reinterpret_cast<const __nv_bfloat162*>(&S[F_HBL + row * 264 + col]);
                z2v[j][hf * 2]     = 2.f * zf[j][hf * 2]     - (__bfloat162float(hh.x) + __bfloat162float(hl.x));
                z2v[j][hf * 2 + 1] = 2.f * zf[j][hf * 2 + 1] - (__bfloat162float(hh.y) + __bfloat162float(hl.y));
            }
        }
        __syncthreads();   // all reads of hbuf done (section 0 + above)
#pragma unroll
        for (int j = 0; j < 8; ++j) {
            int col = wn * 64 + j * 8 + (lane & 3) * 2;
#pragma unroll
            for (int hf = 0; hf < 2; ++hf) {
                int row = wm * 16 + (lane >> 2) + hf * 8;
                __nv_bfloat16 h0, l0, h1, l1;
                bsplit(z2v[j][hf * 2], h0, l0);
                bsplit(z2v[j][hf * 2 + 1], h1, l1);
                __nv_bfloat162 ph; ph.x = h0; ph.y = h1;
                __nv_bfloat162 pl; pl.x = l0; pl.y = l1;
                *reinterpret_cast<__nv_bfloat162*>(&S[F_HBH + row * 264 + col]) = ph;
                *reinterpret_cast<__nv_bfloat162*>(&S[F_HBL + row * 264 + col]) = pl;
            }
        }
    }
    __syncthreads();

    // ---- theta sections 1 (z1) and 2 (z2, in hbuf) ----
    theta_section(sb, S, t, lane, wm, wn, F_Z1H, 256, THh, THl, acc);
    theta_section(sb, S, t, lane, wm, wn, F_HBH, 512, THh, THl, acc);

    // ---- epilogue: relu, write V, write next-layer H ----
#pragma unroll
    for (int j = 0; j < 8; ++j) {
        int col = wn * 64 + j * 8 + (lane & 3) * 2;
#pragma unroll
        for (int hf = 0; hf < 2; ++hf) {
            int row = wm * 16 + (lane >> 2) + hf * 8;
            float v0 = fmaxf(acc[j][hf * 2],     0.f);
            float v1 = fmaxf(acc[j][hf * 2 + 1], 0.f);
            float2 vv = make_float2(v0, v1);
            *reinterpret_cast<float2*>(
                Vout + (((size_t)b * NLAYER + layer) * 64 + row) * 256 + col) = vv;
            if (writeH) {
                __nv_bfloat16 h0, l0, h1, l1;
                bsplit(v0, h0, l0); bsplit(v1, h1, l1);
                __nv_bfloat162 ph; ph.x = h0; ph.y = h1;
                __nv_bfloat162 pl; pl.x = l0; pl.y = l1;
                size_t o = (size_t)(b * 64 + row) * 256 + col;
                *reinterpret_cast<__nv_bfloat162*>(Hhi + o) = ph;
                *reinterpret_cast<__nv_bfloat162*>(Hlo + o) = pl;
            }
        }
    }
}

// ---------------- launcher ----------------
extern "C" void kernel_launch(void* const* d_in, const int* in_sizes, int n_in,
                              void* d_out, int out_size)
{
    const float* x     = (const float*)d_in[0];
    const float* Wq    = (const float*)d_in[1];
    const float* bq    = (const float*)d_in[2];
    const float* Wk    = (const float*)d_in[3];
    const float* bk    = (const float*)d_in[4];
    const float* theta = (const float*)d_in[5];

    float* out  = (float*)d_out;
    float* Vout = out;
    float* Aout = out + VELEMS;

    __nv_bfloat16 *Hhi, *Hlo, *THhi, *THlo;
    float *Qb, *Kb, *Wt;
    cudaGetSymbolAddress((void**)&Hhi, g_Hhi);
    cudaGetSymbolAddress((void**)&Hlo, g_Hlo);
    cudaGetSymbolAddress((void**)&THhi, g_THhi);
    cudaGetSymbolAddress((void**)&THlo, g_THlo);
    cudaGetSymbolAddress((void**)&Qb, g_Q);
    cudaGetSymbolAddress((void**)&Kb, g_K);
    cudaGetSymbolAddress((void**)&Wt, g_Wt);

    cudaFuncSetAttribute(attn_k, cudaFuncAttributeMaxDynamicSharedMemorySize, 49152);
    cudaFuncSetAttribute(qk_tf32, cudaFuncAttributeMaxDynamicSharedMemorySize, QK_SMEM);
    cudaFuncSetAttribute(fused_layer, cudaFuncAttributeMaxDynamicSharedMemorySize, FUSED_SMEM);

    split_x_k<<<16384, 256>>>(x, Hhi, Hlo);
    prep_wt_k<<<512, 256>>>(Wq, Wk, Wt);
    prep_th_k<<<3072, 256>>>(theta, THhi, THlo);

    dim3 qkGrid(2, 512);
    qk_tf32<<<qkGrid, 256, QK_SMEM>>>(x, Wt, bq, Qb);
    qk_tf32<<<qkGrid, 256, QK_SMEM>>>(x, Wt + 65536, bk, Kb);

    attn_k<<<B_SZ, 256, 49152>>>(Qb, Kb, Aout);

    for (int l = 0; l < NLAYER; ++l) {
        fused_layer<<<B_SZ, 512, FUSED_SMEM>>>(
            Aout, THhi + (size_t)l * 196608, THlo + (size_t)l * 196608,
            Hhi, Hlo, Vout, (l < 3) ? 1 : 0, l);
    }
}

// round 10
// speedup vs baseline: 1.0271x; 1.0271x over previous
#include <cuda_runtime.h>
#include <cuda_bf16.h>
#include <math.h>
#include <stdint.h>

#define B_SZ   1024
#define NLAYER 4
#define MROWS  65536
#define VELEMS ((size_t)B_SZ * NLAYER * 64 * 256)

// ---------------- scratch (static device globals; no allocation) ----------------
__device__ __align__(16) __nv_bfloat16 g_Zhi[(size_t)MROWS * 768];
__device__ __align__(16) __nv_bfloat16 g_Zlo[(size_t)MROWS * 768];
__device__ __align__(16) float         g_Q[(size_t)MROWS * 256];
__device__ __align__(16) float         g_K[(size_t)MROWS * 256];
__device__ __align__(16) float         g_Wt[2 * 256 * 256];
__device__ __align__(16) __nv_bfloat16 g_THhi[4 * 256 * 768];
__device__ __align__(16) __nv_bfloat16 g_THlo[4 * 256 * 768];
__device__ __align__(16) __nv_bfloat16 g_LPh[(size_t)B_SZ * 8192];   // [Lt | P] hi per batch
__device__ __align__(16) __nv_bfloat16 g_LPl[(size_t)B_SZ * 8192];   // [Lt | P] lo per batch

// ---------------- helpers ----------------
__device__ __forceinline__ uint32_t smem_u32(const void* p) {
    uint32_t a;
    asm("{ .reg .u64 t; cvta.to.shared.u64 t, %1; cvt.u32.u64 %0, t; }" : "=r"(a) : "l"(p));
    return a;
}
__device__ __forceinline__ void ldsm_x4(uint32_t* r, uint32_t a) {
    asm volatile("ldmatrix.sync.aligned.m8n8.x4.shared.b16 {%0,%1,%2,%3}, [%4];"
                 : "=r"(r[0]), "=r"(r[1]), "=r"(r[2]), "=r"(r[3]) : "r"(a));
}
__device__ __forceinline__ void ldsm_x4t(uint32_t* r, uint32_t a) {
    asm volatile("ldmatrix.sync.aligned.m8n8.x4.trans.shared.b16 {%0,%1,%2,%3}, [%4];"
                 : "=r"(r[0]), "=r"(r[1]), "=r"(r[2]), "=r"(r[3]) : "r"(a));
}
__device__ __forceinline__ void mma_bf16(float* d, const uint32_t* a, uint32_t b0, uint32_t b1) {
    asm volatile("mma.sync.aligned.m16n8k16.row.col.f32.bf16.bf16.f32 "
                 "{%0,%1,%2,%3}, {%4,%5,%6,%7}, {%8,%9}, {%0,%1,%2,%3};"
                 : "+f"(d[0]), "+f"(d[1]), "+f"(d[2]), "+f"(d[3])
                 : "r"(a[0]), "r"(a[1]), "r"(a[2]), "r"(a[3]), "r"(b0), "r"(b1));
}
__device__ __forceinline__ void mma_tf32(float* d, const uint32_t* a, uint32_t b0, uint32_t b1) {
    asm volatile("mma.sync.aligned.m16n8k8.row.col.f32.tf32.tf32.f32 "
                 "{%0,%1,%2,%3}, {%4,%5,%6,%7}, {%8,%9}, {%0,%1,%2,%3};"
                 : "+f"(d[0]), "+f"(d[1]), "+f"(d[2]), "+f"(d[3])
                 : "r"(a[0]), "r"(a[1]), "r"(a[2]), "r"(a[3]), "r"(b0), "r"(b1));
}
__device__ __forceinline__ uint32_t f2tf32(float f) {
    uint32_t r; asm("cvt.rna.tf32.f32 %0, %1;" : "=r"(r) : "f"(f)); return r;
}
__device__ __forceinline__ void bsplit(float v, __nv_bfloat16& h, __nv_bfloat16& l) {
    h = __float2bfloat16(v);
    l = __float2bfloat16(v - __bfloat162float(h));
}

// ---------------- prep kernels ----------------
__global__ __launch_bounds__(256) void split_x_k(
    const float* __restrict__ x, __nv_bfloat16* __restrict__ zhi,
    __nv_bfloat16* __restrict__ zlo)
{
    int e = blockIdx.x * 256 + threadIdx.x;
    int m = e >> 6, q = e & 63;
    float4 v = reinterpret_cast<const float4*>(x)[e];
    __nv_bfloat16 h0, l0, h1, l1, h2, l2, h3, l3;
    bsplit(v.x, h0, l0); bsplit(v.y, h1, l1);
    bsplit(v.z, h2, l2); bsplit(v.w, h3, l3);
    size_t o = (size_t)m * 768 + q * 4;
    __nv_bfloat162 a; a.x = h0; a.y = h1;
    __nv_bfloat162 b; b.x = h2; b.y = h3;
    __nv_bfloat162 c; c.x = l0; c.y = l1;
    __nv_bfloat162 d; d.x = l2; d.y = l3;
    reinterpret_cast<__nv_bfloat162*>(zhi + o)[0] = a;
    reinterpret_cast<__nv_bfloat162*>(zhi + o)[1] = b;
    reinterpret_cast<__nv_bfloat162*>(zlo + o)[0] = c;
    reinterpret_cast<__nv_bfloat162*>(zlo + o)[1] = d;
}

__global__ __launch_bounds__(256) void prep_wt_k(
    const float* __restrict__ Wq, const float* __restrict__ Wk, float* __restrict__ Wt)
{
    int i = blockIdx.x * 256 + threadIdx.x;   // 131072
    int mat = i >> 16, rem = i & 65535;
    int n = rem >> 8, k = rem & 255;
    Wt[i] = (mat ? Wk : Wq)[k * 256 + n];
}

__global__ __launch_bounds__(256) void prep_th_k(
    const float* __restrict__ theta,
    __nv_bfloat16* __restrict__ thi, __nv_bfloat16* __restrict__ tlo)
{
    int idx = blockIdx.x * 256 + threadIdx.x;   // 786432 total
    int l = idx / 196608, rem = idx % 196608;
    int n = rem / 768, k = rem % 768;
    float v = theta[(size_t)l * 196608 + (size_t)k * 256 + n];
    __nv_bfloat16 h, lo; bsplit(v, h, lo);
    thi[(size_t)l * 196608 + (size_t)n * 768 + k] = h;
    tlo[(size_t)l * 196608 + (size_t)n * 768 + k] = lo;
}

// ---------------- per-batch Lt/P precompute: Lt = -A, P = 2*A*A^T - I (A symmetric) ----------------
__global__ __launch_bounds__(256) void prep_ltp(
    const float* __restrict__ Aglob,
    __nv_bfloat16* __restrict__ LPh, __nv_bfloat16* __restrict__ LPl)
{
    __shared__ float As[4096];
    const int b = blockIdx.x, t = threadIdx.x;
    const float4* Ab = reinterpret_cast<const float4*>(Aglob + (size_t)b * 4096);
    float4* Ad = reinterpret_cast<float4*>(As);
    for (int e = t; e < 1024; e += 256) Ad[e] = Ab[e];
    __syncthreads();

    size_t base = (size_t)b * 8192;
    for (int e = t; e < 4096; e += 256) {
        int i = e >> 6, j = e & 63;
        __nv_bfloat16 h, l;
        bsplit(-As[e], h, l);
        LPh[base + e] = h;
        LPl[base + e] = l;
        const float4* ri = reinterpret_cast<const float4*>(As + i * 64);
        const float4* rj = reinterpret_cast<const float4*>(As + j * 64);
        float s = 0.f;
#pragma unroll
        for (int k = 0; k < 16; ++k) {
            float4 a = ri[k], c = rj[k];
            s += a.x * c.x + a.y * c.y + a.z * c.z + a.w * c.w;
        }
        float p = 2.f * s - (i == j ? 1.f : 0.f);
        bsplit(p, h, l);
        LPh[base + 4096 + e] = h;
        LPl[base + 4096 + e] = l;
    }
}

// ---------------- QK projection: 3xTF32 mma, single launch for Q and K ----------------
#define QK_SMEM (18432 * 4)

__global__ __launch_bounds__(256, 2) void qk_tf32(
    const float* __restrict__ X, const float* __restrict__ Wt,
    const float* __restrict__ bq, const float* __restrict__ bk,
    float* __restrict__ Qo, float* __restrict__ Ko)
{
    extern __shared__ float sm[];
    float* xs_h = sm;
    float* xs_l = sm + 4608;
    float* ws_h = sm + 9216;
    float* ws_l = sm + 13824;

    const int t = threadIdx.x, lane = t & 31, w = t >> 5;
    const int wm = w >> 2, wn = w & 3;
    const int m0 = blockIdx.y * 128, n0 = blockIdx.x * 128;

    float acc[4][4][4];
#pragma unroll
    for (int i = 0; i < 4; ++i)
#pragma unroll
        for (int j = 0; j < 4; ++j)
#pragma unroll
            for (int q = 0; q < 4; ++q) acc[i][j][q] = 0.f;

    float4 px[4], pw[4];
#pragma unroll
    for (int i = 0; i < 4; ++i) {
        int e = t + i * 256, r = e >> 3, q = e & 7;
        px[i] = *reinterpret_cast<const float4*>(X  + (size_t)(m0 + r) * 256 + q * 4);
        pw[i] = *reinterpret_cast<const float4*>(Wt + (size_t)(n0 + r) * 256 + q * 4);
    }

    for (int c = 0; c < 8; ++c) {
        __syncthreads();
#pragma unroll
        for (int i = 0; i < 4; ++i) {
            int e = t + i * 256, r = e >> 3, q = e & 7;
            int base = r * 36 + q * 4;
            float vx[4] = {px[i].x, px[i].y, px[i].z, px[i].w};
            float vw[4] = {pw[i].x, pw[i].y, pw[i].z, pw[i].w};
#pragma unroll
            for (int j = 0; j < 4; ++j) {
                float xh = __uint_as_float(f2tf32(vx[j]));
                xs_h[base + j] = xh;
                xs_l[base + j] = __uint_as_float(f2tf32(vx[j] - xh));
                float wh = __uint_as_float(f2tf32(vw[j]));
                ws_h[base + j] = wh;
                ws_l[base + j] = __uint_as_float(f2tf32(vw[j] - wh));
            }
        }
        if (c < 7) {
#pragma unroll
            for (int i = 0; i < 4; ++i) {
                int e = t + i * 256, r = e >> 3, q = e & 7;
                px[i] = *reinterpret_cast<const float4*>(
                    X  + (size_t)(m0 + r) * 256 + (c + 1) * 32 + q * 4);
                pw[i] = *reinterpret_cast<const float4*>(
                    Wt + (size_t)(n0 + r) * 256 + (c + 1) * 32 + q * 4);
            }
        }
        __syncthreads();

#pragma unroll
        for (int ks = 0; ks < 4; ++ks) {
            const int cc = ks * 8 + (lane & 3);
            uint32_t bh[4][2], bl[4][2];
#pragma unroll
            for (int nt = 0; nt < 4; ++nt) {
                int n = wn * 32 + nt * 8 + (lane >> 2);
                bh[nt][0] = __float_as_uint(ws_h[n * 36 + cc]);
                bh[nt][1] = __float_as_uint(ws_h[n * 36 + cc + 4]);
                bl[nt][0] = __float_as_uint(ws_l[n * 36 + cc]);
                bl[nt][1] = __float_as_uint(ws_l[n * 36 + cc + 4]);
            }
#pragma unroll
            for (int mt = 0; mt < 4; ++mt) {
                int r0 = wm * 64 + mt * 16 + (lane >> 2);
                uint32_t ah[4], al[4];
                ah[0] = __float_as_uint(xs_h[r0 * 36 + cc]);
                ah[1] = __float_as_uint(xs_h[(r0 + 8) * 36 + cc]);
                ah[2] = __float_as_uint(xs_h[r0 * 36 + cc + 4]);
                ah[3] = __float_as_uint(xs_h[(r0 + 8) * 36 + cc + 4]);
                al[0] = __float_as_uint(xs_l[r0 * 36 + cc]);
                al[1] = __float_as_uint(xs_l[(r0 + 8) * 36 + cc]);
                al[2] = __float_as_uint(xs_l[r0 * 36 + cc + 4]);
                al[3] = __float_as_uint(xs_l[(r0 + 8) * 36 + cc + 4]);
#pragma unroll
                for (int nt = 0; nt < 4; ++nt) {
                    mma_tf32(acc[mt][nt], ah, bh[nt][0], bh[nt][1]);
                    mma_tf32(acc[mt][nt], ah, bl[nt][0], bl[nt][1]);
                    mma_tf32(acc[mt][nt], al, bh[nt][0], bh[nt][1]);
                }
            }
        }
    }

#pragma unroll
    for (int mt = 0; mt < 4; ++mt)
#pragma unroll
        for (int nt = 0; nt < 4; ++nt) {
            int n_g = n0 + wn * 32 + nt * 8 + (lane & 3) * 2;
            const float* bsrc = (n_g < 256) ? bq : bk;
            float* dst = (n_g < 256) ? Qo : Ko;
            int nc = n_g & 255;
            float b0 = bsrc[nc], b1 = bsrc[nc + 1];
#pragma unroll
            for (int hf = 0; hf < 2; ++hf) {
                int m = m0 + wm * 64 + mt * 16 + (lane >> 2) + hf * 8;
                float2 vv = make_float2(acc[mt][nt][hf * 2] + b0,
                                        acc[mt][nt][hf * 2 + 1] + b1);
                *reinterpret_cast<float2*>(dst + (size_t)m * 256 + nc) = vv;
            }
        }
}

// ---------------- attention -> normalized adjacency (proven R8) ----------------
__global__ __launch_bounds__(256) void attn_k(
    const float* __restrict__ Q, const float* __restrict__ Kmat,
    float* __restrict__ Aout)
{
    extern __shared__ float sm[];
    float* qs  = sm;
    float* ks  = sm + 4096;
    float* adj = sm + 8192;
    __shared__ float deg[64];

    const int b = blockIdx.x, t = threadIdx.x;
    const int i = t >> 2, g = t & 3;

    for (int e = t; e < 4096; e += 256) adj[e] = 0.f;

    for (int h = 0; h < 4; ++h) {
        __syncthreads();
        for (int e = t; e < 4096; e += 256) {
            int n = e >> 6, d = e & 63;
            size_t base = ((size_t)b * 64 + n) * 256 + h * 64 + d;
            qs[e] = Q[base];
            ks[e] = Kmat[base];
        }
        __syncthreads();

        float s[16];
#pragma unroll
        for (int jj = 0; jj < 16; ++jj) s[jj] = 0.f;
        for (int d = 0; d < 64; ++d) {
            float qv = qs[i * 64 + d];
#pragma unroll
            for (int jj = 0; jj < 16; ++jj)
                s[jj] += qv * ks[(g * 16 + jj) * 64 + d];
        }
        float mx = -INFINITY;
#pragma unroll
        for (int jj = 0; jj < 16; ++jj) { s[jj] *= 1.25e8f; mx = fmaxf(mx, s[jj]); }
        mx = fmaxf(mx, __shfl_xor_sync(0xffffffffu, mx, 1));
        mx = fmaxf(mx, __shfl_xor_sync(0xffffffffu, mx, 2));
        float sum = 0.f;
#pragma unroll
        for (int jj = 0; jj < 16; ++jj) { s[jj] = __expf(s[jj] - mx); sum += s[jj]; }
        sum += __shfl_xor_sync(0xffffffffu, sum, 1);
        sum += __shfl_xor_sync(0xffffffffu, sum, 2);
        float inv = 0.25f / sum;
#pragma unroll
        for (int jj = 0; jj < 16; ++jj)
            adj[i * 64 + g * 16 + jj] += s[jj] * inv;
    }
    __syncthreads();

    float sv[16];
#pragma unroll
    for (int jj = 0; jj < 16; ++jj) {
        int j = g * 16 + jj;
        sv[jj] = 0.5f * (adj[i * 64 + j] + adj[j * 64 + i]);
    }
    __syncthreads();
#pragma unroll
    for (int jj = 0; jj < 16; ++jj) adj[i * 64 + g * 16 + jj] = sv[jj];

    float ds = 0.f;
#pragma unroll
    for (int jj = 0; jj < 16; ++jj) ds += sv[jj];
    ds += __shfl_xor_sync(0xffffffffu, ds, 1);
    ds += __shfl_xor_sync(0xffffffffu, ds, 2);
    if (g == 0) deg[i] = rsqrtf(ds);
    __syncthreads();

    float di = deg[i];
#pragma unroll
    for (int jj = 0; jj < 16; ++jj) {
        int j = g * 16 + jj;
        Aout[(size_t)b * 4096 + i * 64 + j] = di * adj[i * 64 + j] * deg[j];
    }
}

// ---------------- Chebyshev z-build: z1 = Lt@h, z2 = P@h (independent, single phase) ----------------
// smem bf16 elem offsets: Lt hi/lo (64x72), P hi/lo (64x72), h hi/lo (64x136).
#define C_LTH 0
#define C_LTL 4608
#define C_PH  9216
#define C_PL  13824
#define C_HH  18432
#define C_HL  27136
#define CHEB2_SMEM (35840 * 2)

__device__ __forceinline__ void zstep2(
    uint32_t sb, int wm, int wn, int lane, int aOff, float acc[2][4][4])
{
#pragma unroll
    for (int i = 0; i < 2; ++i)
#pragma unroll
        for (int j = 0; j < 4; ++j)
#pragma unroll
            for (int q = 0; q < 4; ++q) acc[i][j][q] = 0.f;

#pragma unroll
    for (int ks = 0; ks < 4; ++ks) {
        uint32_t ahr[2][4], alr[2][4];
#pragma unroll
        for (int mt = 0; mt < 2; ++mt) {
            uint32_t ao = sb + 2 * (aOff + (wm * 32 + mt * 16 + (lane & 15)) * 72
                                    + ks * 16 + (lane >> 4) * 8);
            ldsm_x4(ahr[mt], ao);
            ldsm_x4(alr[mt], ao + 2 * 4608);
        }
        uint32_t bh[2][4], bl[2][4];
#pragma unroll
        for (int np = 0; np < 2; ++np) {
            uint32_t bo = sb + 2 * ((ks * 16 + (lane & 15)) * 136
                                    + wn * 32 + np * 16 + (lane >> 4) * 8);
            ldsm_x4t(bh[np], bo + 2 * C_HH);
            ldsm_x4t(bl[np], bo + 2 * C_HL);
        }
#pragma unroll
        for (int mt = 0; mt < 2; ++mt)
#pragma unroll
            for (int np = 0; np < 2; ++np)
#pragma unroll
                for (int s = 0; s < 2; ++s) {
                    int nt = np * 2 + s;
                    mma_bf16(acc[mt][nt], ahr[mt], bh[np][2 * s], bh[np][2 * s + 1]);
                    mma_bf16(acc[mt][nt], ahr[mt], bl[np][2 * s], bl[np][2 * s + 1]);
                    mma_bf16(acc[mt][nt], alr[mt], bh[np][2 * s], bh[np][2 * s + 1]);
                }
    }
}

__global__ __launch_bounds__(256, 2) void cheb2(
    const __nv_bfloat16* __restrict__ LPh, const __nv_bfloat16* __restrict__ LPl,
    __nv_bfloat16* __restrict__ zhi, __nv_bfloat16* __restrict__ zlo)
{
    extern __shared__ __nv_bfloat16 S[];
    const uint32_t sb = smem_u32(S);
    const int b = blockIdx.y, f0 = blockIdx.x * 128;
    const int t = threadIdx.x, lane = t & 31, w = t >> 5;
    const int wm = w >> 2, wn = w & 3;

    // copy Lt and P (hi/lo) into padded smem
    {
        size_t base = (size_t)b * 8192;
#pragma unroll
        for (int i = 0; i < 4; ++i) {
            int e = i * 256 + t;          // 0..1023: mat(2) x row(64) x seg(8)
            int mat = e >> 9, r = (e >> 8 * 0 >> 3) & 63, q = e & 7;
            r = (e >> 3) & 63;
            size_t src = base + (size_t)mat * 4096 + r * 64 + q * 8;
            int dst = (mat ? C_PH : C_LTH) + r * 72 + q * 8;
            *reinterpret_cast<uint4*>(&S[dst]) =
                *reinterpret_cast<const uint4*>(LPh + src);
            *reinterpret_cast<uint4*>(&S[dst + 4608]) =
                *reinterpret_cast<const uint4*>(LPl + src);
        }
    }
    // h slice from Z cols 0..255
    {
#pragma unroll
        for (int i = 0; i < 4; ++i) {
            int e = i * 256 + t;
            int r = e >> 4, q = (e & 15) * 8;
            size_t src = (size_t)(b * 64 + r) * 768 + f0 + q;
            *reinterpret_cast<uint4*>(&S[C_HH + r * 136 + q]) =
                *reinterpret_cast<const uint4*>(zhi + src);
            *reinterpret_cast<uint4*>(&S[C_HL + r * 136 + q]) =
                *reinterpret_cast<const uint4*>(zlo + src);
        }
    }
    __syncthreads();

    float a1[2][4][4], a2[2][4][4];
    zstep2(sb, wm, wn, lane, C_LTH, a1);   // z1 = Lt @ h
    zstep2(sb, wm, wn, lane, C_PH,  a2);   // z2 = P  @ h

#pragma unroll
    for (int mt = 0; mt < 2; ++mt)
#pragma unroll
        for (int nt = 0; nt < 4; ++nt) {
            int col = wn * 32 + nt * 8 + (lane & 3) * 2;
#pragma unroll
            for (int hf = 0; hf < 2; ++hf) {
                int row = wm * 32 + mt * 16 + (lane >> 2) + hf * 8;
                size_t zbase = (size_t)(b * 64 + row) * 768 + f0 + col;
                __nv_bfloat16 h0, l0, h1, l1;
                bsplit(a1[mt][nt][hf * 2],     h0, l0);
                bsplit(a1[mt][nt][hf * 2 + 1], h1, l1);
                __nv_bfloat162 ph; ph.x = h0; ph.y = h1;
                __nv_bfloat162 pl; pl.x = l0; pl.y = l1;
                *reinterpret_cast<__nv_bfloat162*>(zhi + zbase + 256) = ph;
                *reinterpret_cast<__nv_bfloat162*>(zlo + zbase + 256) = pl;
                bsplit(a2[mt][nt][hf * 2],     h0, l0);
                bsplit(a2[mt][nt][hf * 2 + 1], h1, l1);
                ph.x = h0; ph.y = h1;
                pl.x = l0; pl.y = l1;
                *reinterpret_cast<__nv_bfloat162*>(zhi + zbase + 512) = ph;
                *reinterpret_cast<__nv_bfloat162*>(zlo + zbase + 512) = pl;
            }
        }
}

// ---------------- theta GEMM: bf16x3 mma, M=128 N=128, double-buffered (proven R8) ----------------
#define TH_SMEM (40960 * 2)

__global__ __launch_bounds__(512, 1) void theta_mma(
    const __nv_bfloat16* __restrict__ Zhi, const __nv_bfloat16* __restrict__ Zlo,
    const __nv_bfloat16* __restrict__ THh, const __nv_bfloat16* __restrict__ THl,
    float* __restrict__ Vout, __nv_bfloat16* __restrict__ zhi,
    __nv_bfloat16* __restrict__ zlo, int writeZ, int layer)
{
    extern __shared__ __nv_bfloat16 S[];   // 2 x 20480
    const uint32_t sb = smem_u32(S);
    const int t = threadIdx.x, lane = t & 31, w = t >> 5;
    const int wm = w >> 2, wn = w & 3;
    const int m0 = blockIdx.y * 128, n0 = blockIdx.x * 128;

    float acc[2][4][4];
#pragma unroll
    for (int i = 0; i < 2; ++i)
#pragma unroll
        for (int j = 0; j < 4; ++j)
#pragma unroll
            for (int q = 0; q < 4; ++q) acc[i][j][q] = 0.f;

    const int ar = t >> 2, as = (t & 3) * 8;
    const size_t aSrc = (size_t)(m0 + ar) * 768 + as;
    const size_t bSrc = (size_t)(n0 + ar) * 768 + as;
    const int dOff = ar * 40 + as;

    uint4 pa0 = *reinterpret_cast<const uint4*>(Zhi + aSrc);
    uint4 pa1 = *reinterpret_cast<const uint4*>(Zlo + aSrc);
    uint4 pb0 = *reinterpret_cast<const uint4*>(THh + bSrc);
    uint4 pb1 = *reinterpret_cast<const uint4*>(THl + bSrc);
    *reinterpret_cast<uint4*>(&S[dOff])         = pa0;
    *reinterpret_cast<uint4*>(&S[5120 + dOff])  = pa1;
    *reinterpret_cast<uint4*>(&S[10240 + dOff]) = pb0;
    *reinterpret_cast<uint4*>(&S[15360 + dOff]) = pb1;
    __syncthreads();

    const uint32_t aAddr = sb + 2 * ((wm * 32 + (lane & 15)) * 40 + (lane >> 4) * 8);
    const uint32_t bAddr = sb + 2 * (10240 + (wn * 32 + (lane & 15)) * 40 + (lane >> 4) * 8);

    for (int c = 0; c < 24; ++c) {
        const int cur = c & 1;
        const uint32_t bOff = cur * 40960;   // bytes
        if (c < 23) {
            size_t ka = aSrc + (c + 1) * 32, kb = bSrc + (c + 1) * 32;
            pa0 = *reinterpret_cast<const uint4*>(Zhi + ka);
            pa1 = *reinterpret_cast<const uint4*>(Zlo + ka);
            pb0 = *reinterpret_cast<const uint4*>(THh + kb);
            pb1 = *reinterpret_cast<const uint4*>(THl + kb);
        }

#pragma unroll
        for (int ks = 0; ks < 2; ++ks) {
            uint32_t ahr[2][4], alr[2][4], bhr[2][4], blr[2][4];
#pragma unroll
            for (int mt = 0; mt < 2; ++mt) {
                uint32_t off = bOff + 2 * (mt * 16 * 40 + ks * 16);
                ldsm_x4(ahr[mt], aAddr + off);
                ldsm_x4(alr[mt], aAddr + 2 * 5120 + off);
            }
#pragma unroll
            for (int np = 0; np < 2; ++np) {
                uint32_t off = bOff + 2 * (np * 16 * 40 + ks * 16);
                ldsm_x4(bhr[np], bAddr + off);
                ldsm_x4(blr[np], bAddr + 2 * 5120 + off);
            }
#pragma unroll
            for (int mt = 0; mt < 2; ++mt)
#pragma unroll
                for (int nt = 0; nt < 4; ++nt) {
                    int np = nt >> 1, s = nt & 1;
                    mma_bf16(acc[mt][nt], ahr[mt], bhr[np][s], bhr[np][s + 2]);
                    mma_bf16(acc[mt][nt], ahr[mt], blr[np][s], blr[np][s + 2]);
                    mma_bf16(acc[mt][nt], alr[mt], bhr[np][s], bhr[np][s + 2]);
                }
        }

        if (c < 23) {
            int o = (cur ^ 1) * 20480 + dOff;
            *reinterpret_cast<uint4*>(&S[o])         = pa0;
            *reinterpret_cast<uint4*>(&S[o + 5120])  = pa1;
            *reinterpret_cast<uint4*>(&S[o + 10240]) = pb0;
            *reinterpret_cast<uint4*>(&S[o + 15360]) = pb1;
            __syncthreads();
        }
    }

#pragma unroll
    for (int mt = 0; mt < 2; ++mt)
#pragma unroll
        for (int nt = 0; nt < 4; ++nt) {
            int np = nt >> 1, s = nt & 1;
            int n = n0 + wn * 32 + np * 16 + s * 8 + (lane & 3) * 2;
#pragma unroll
            for (int hf = 0; hf < 2; ++hf) {
                int m = m0 + wm * 32 + mt * 16 + (lane >> 2) + hf * 8;
                float v0 = fmaxf(acc[mt][nt][hf * 2],     0.f);
                float v1 = fmaxf(acc[mt][nt][hf * 2 + 1], 0.f);
                int b = m >> 6, nd = m & 63;
                float2 vv = make_float2(v0, v1);
                *reinterpret_cast<float2*>(
                    Vout + ((size_t)(b * NLAYER + layer) * 64 + nd) * 256 + n) = vv;
                if (writeZ) {
                    __nv_bfloat16 h0, l0, h1, l1;
                    bsplit(v0, h0, l0); bsplit(v1, h1, l1);
                    __nv_bfloat162 ph; ph.x = h0; ph.y = h1;
                    __nv_bfloat162 pl; pl.x = l0; pl.y = l1;
                    *reinterpret_cast<__nv_bfloat162*>(zhi + (size_t)m * 768 + n) = ph;
                    *reinterpret_cast<__nv_bfloat162*>(zlo + (size_t)m * 768 + n) = pl;
                }
            }
        }
}

// ---------------- launcher ----------------
extern "C" void kernel_launch(void* const* d_in, const int* in_sizes, int n_in,
                              void* d_out, int out_size)
{
    const float* x     = (const float*)d_in[0];
    const float* Wq    = (const float*)d_in[1];
    const float* bq    = (const float*)d_in[2];
    const float* Wk    = (const float*)d_in[3];
    const float* bk    = (const float*)d_in[4];
    const float* theta = (const float*)d_in[5];

    float* out  = (float*)d_out;
    float* Vout = out;
    float* Aout = out + VELEMS;

    __nv_bfloat16 *Zhi, *Zlo, *THhi, *THlo, *LPh, *LPl;
    float *Qb, *Kb, *Wt;
    cudaGetSymbolAddress((void**)&Zhi, g_Zhi);
    cudaGetSymbolAddress((void**)&Zlo, g_Zlo);
    cudaGetSymbolAddress((void**)&THhi, g_THhi);
    cudaGetSymbolAddress((void**)&THlo, g_THlo);
    cudaGetSymbolAddress((void**)&LPh, g_LPh);
    cudaGetSymbolAddress((void**)&LPl, g_LPl);
    cudaGetSymbolAddress((void**)&Qb, g_Q);
    cudaGetSymbolAddress((void**)&Kb, g_K);
    cudaGetSymbolAddress((void**)&Wt, g_Wt);

    cudaFuncSetAttribute(attn_k, cudaFuncAttributeMaxDynamicSharedMemorySize, 49152);
    cudaFuncSetAttribute(qk_tf32, cudaFuncAttributeMaxDynamicSharedMemorySize, QK_SMEM);
    cudaFuncSetAttribute(cheb2, cudaFuncAttributeMaxDynamicSharedMemorySize, CHEB2_SMEM);
    cudaFuncSetAttribute(theta_mma, cudaFuncAttributeMaxDynamicSharedMemorySize, TH_SMEM);

    split_x_k<<<16384, 256>>>(x, Zhi, Zlo);
    prep_wt_k<<<512, 256>>>(Wq, Wk, Wt);
    prep_th_k<<<3072, 256>>>(theta, THhi, THlo);

    dim3 qkGrid(4, 512);
    qk_tf32<<<qkGrid, 256, QK_SMEM>>>(x, Wt, bq, bk, Qb, Kb);

    attn_k<<<B_SZ, 256, 49152>>>(Qb, Kb, Aout);
    prep_ltp<<<B_SZ, 256>>>(Aout, LPh, LPl);

    dim3 chGrid(2, B_SZ);
    dim3 thGrid(2, 512);
    for (int l = 0; l < NLAYER; ++l) {
        cheb2<<<chGrid, 256, CHEB2_SMEM>>>(LPh, LPl, Zhi, Zlo);
        theta_mma<<<thGrid, 512, TH_SMEM>>>(Zhi, Zlo,
                                   THhi + (size_t)l * 196608, THlo + (size_t)l * 196608,
                                   Vout, Zhi, Zlo, (l < 3) ? 1 : 0, l);
    }
}